// round 15
// baseline (speedup 1.0000x reference)
#include <cuda_runtime.h>
#include <cuda_bf16.h>
#include <math.h>
#include <stdint.h>

#define NN   50000
#define EE   800000
#define FF   768
#define HH   256
#define AA   128
#define AHD  4
#define NCLS 7

// pre-split weight buffer offsets (uint32 words)
#define OFF_WIN 0
#define OFF_GW1 98304
#define OFF_GW2 163840
#define OFF_AW1 229376
#define WSPLIT_TOTAL 294912

// ---------------- scratch (no allocations allowed) ----------------
__device__ __align__(16) float g_h[(size_t)NN * HH];
__device__ __align__(16) float g_agg[(size_t)NN * HH];
__device__ __align__(16) float g_t[(size_t)NN * HH];
__device__ __align__(16) uint32_t g_wbh[WSPLIT_TOTAL];
__device__ __align__(16) uint32_t g_wbl[WSPLIT_TOTAL];
__device__ int   g_deg[NN];
__device__ int   g_rowstart[NN + 1];
__device__ int   g_cursor[NN];
__device__ int   g_srclist[EE];
__device__ float g_logits[AHD * NN];
__device__ float g_smax[AHD];
__device__ float g_srsum[AHD];
__device__ float g_z[AHD * HH];

// ---------------- bf16 split helper ----------------
__device__ __forceinline__ void split2(float x, float y, uint32_t& hi, uint32_t& lo) {
    __nv_bfloat16 hx = __float2bfloat16(x), hy = __float2bfloat16(y);
    float rx = x - __bfloat162float(hx), ry = y - __bfloat162float(hy);
    __nv_bfloat16 lx = __float2bfloat16(rx), ly = __float2bfloat16(ry);
    hi = (uint32_t)(*(unsigned short*)&hx) | ((uint32_t)(*(unsigned short*)&hy) << 16);
    lo = (uint32_t)(*(unsigned short*)&lx) | ((uint32_t)(*(unsigned short*)&ly) << 16);
}

// ---------------- weight pre-split: [K][N] fp32 -> [N][K/2] packed hi/lo ----------------
__global__ void wsplit_kernel(const float* __restrict__ W_in, const float* __restrict__ gW1,
                              const float* __restrict__ gW2, const float* __restrict__ aW1) {
    int idx = blockIdx.x * blockDim.x + threadIdx.x;
    if (idx >= WSPLIT_TOTAL) return;
    const float* B;
    int N, Kw, dstOff, local;
    if (idx < OFF_GW1) {
        B = W_in; N = 256; Kw = 384; dstOff = OFF_WIN; local = idx;
    } else if (idx < OFF_GW2) {
        int t = idx - OFF_GW1;
        int l = t >> 15;           // /32768
        local = t & 32767;
        B = gW1 + l * 65536; N = 256; Kw = 128; dstOff = OFF_GW1 + l * 32768;
    } else if (idx < OFF_AW1) {
        int t = idx - OFF_GW2;
        int l = t >> 15;
        local = t & 32767;
        B = gW2 + l * 65536; N = 256; Kw = 128; dstOff = OFF_GW2 + l * 32768;
    } else {
        int t = idx - OFF_AW1;
        int h = t >> 14;           // /16384
        local = t & 16383;
        B = aW1 + h * 32768; N = 128; Kw = 128; dstOff = OFF_AW1 + h * 16384;
    }
    int kp = local / N, n = local - kp * N;
    float v0 = B[(size_t)(2 * kp) * N + n];
    float v1 = B[(size_t)(2 * kp + 1) * N + n];
    uint32_t hi, lo;
    split2(v0, v1, hi, lo);
    g_wbh[dstOff + n * Kw + kp] = hi;
    g_wbl[dstOff + n * Kw + kp] = lo;
}

// ---------------- small utility kernels ----------------
__global__ void zero_kernel() {
    int i = blockIdx.x * blockDim.x + threadIdx.x;
    if (i < NN) g_deg[i] = 0;
    if (i < AHD * HH) g_z[i] = 0.f;
}

__global__ void hist_kernel(const int* __restrict__ ei) {
    int e = blockIdx.x * blockDim.x + threadIdx.x;
    if (e < EE) atomicAdd(&g_deg[ei[EE + e]], 1);
}

__global__ __launch_bounds__(1024) void scan_kernel() {
    __shared__ int ssum[1024];
    int tid = threadIdx.x;
    const int CH = (NN + 1023) / 1024;
    int base = tid * CH;
    int s = 0;
    for (int i = 0; i < CH; i++) {
        int idx = base + i;
        if (idx < NN) s += g_deg[idx];
    }
    ssum[tid] = s;
    __syncthreads();
    for (int off = 1; off < 1024; off <<= 1) {
        int v = 0;
        if (tid >= off) v = ssum[tid - off];
        __syncthreads();
        ssum[tid] += v;
        __syncthreads();
    }
    int run = (tid == 0) ? 0 : ssum[tid - 1];
    for (int i = 0; i < CH; i++) {
        int idx = base + i;
        if (idx < NN) {
            g_rowstart[idx] = run;
            g_cursor[idx]   = run;
            run += g_deg[idx];
        }
    }
    if (tid == 1023) g_rowstart[NN] = run;
}

__global__ void fill_kernel(const int* __restrict__ ei) {
    int e = blockIdx.x * blockDim.x + threadIdx.x;
    if (e < EE) {
        int d = ei[EE + e];
        int pos = atomicAdd(&g_cursor[d], 1);
        g_srclist[pos] = ei[e];
    }
}

// ---------------- GIN aggregation: one warp per destination node ----------------
__device__ __forceinline__ float4 f4add(float4 a, float4 b) {
    return make_float4(a.x + b.x, a.y + b.y, a.z + b.z, a.w + b.w);
}

__global__ __launch_bounds__(256) void gin_agg_kernel(const float* __restrict__ epsv, int layer) {
    int gtid = blockIdx.x * blockDim.x + threadIdx.x;
    int node = gtid >> 5;
    int lane = gtid & 31;
    if (node >= NN) return;
    int s = g_rowstart[node];
    int e = g_rowstart[node + 1];
    float4 acc0 = make_float4(0, 0, 0, 0);
    float4 acc1 = make_float4(0, 0, 0, 0);
    for (int i = s; i < e; i++) {
        int src = g_srclist[i];
        const float4* r = (const float4*)(g_h + (size_t)src * HH);
        acc0 = f4add(acc0, r[lane]);
        acc1 = f4add(acc1, r[lane + 32]);
    }
    float ep = 1.f + epsv[layer];
    const float4* hr = (const float4*)(g_h + (size_t)node * HH);
    float4 h0 = hr[lane], h1 = hr[lane + 32];
    float4* ar = (float4*)(g_agg + (size_t)node * HH);
    ar[lane]      = make_float4(ep * h0.x + acc0.x, ep * h0.y + acc0.y, ep * h0.z + acc0.z, ep * h0.w + acc0.w);
    ar[lane + 32] = make_float4(ep * h1.x + acc1.x, ep * h1.y + acc1.y, ep * h1.z + acc1.z, ep * h1.w + acc1.w);
}

// ---------------- split-bf16 tensor-core GEMM, 128x128 tile ----------------
// C[M,N] = A[M,K] @ B[K,N]; B pre-split/transposed in g_wbh/g_wbl at word offset bOff.
// 8 warps: warpM 0-3 (32 rows), warpN 0-1 (64 cols). acc[2][8][4].
// MODE 0: C = A@B + bias
// MODE 1: logits[head][row] = sum_col tanh(acc + b1)*w2  (single col tile, N=128)

__device__ __forceinline__ void mma16(float* d, const uint32_t* a, const uint32_t* b) {
    asm volatile(
        "mma.sync.aligned.m16n8k16.row.col.f32.bf16.bf16.f32 "
        "{%0,%1,%2,%3}, {%4,%5,%6,%7}, {%8,%9}, {%0,%1,%2,%3};"
        : "+f"(d[0]), "+f"(d[1]), "+f"(d[2]), "+f"(d[3])
        : "r"(a[0]), "r"(a[1]), "r"(a[2]), "r"(a[3]), "r"(b[0]), "r"(b[1]));
}

#define AST 17
#define BST 20

template <int MODE>
__global__ __launch_bounds__(256, 2) void gemm_bf16_kernel(
    const float* __restrict__ A, int bOff, int Kw,
    const float* __restrict__ bias, float* __restrict__ C,
    int M, int N, int K,
    const float* __restrict__ ab1, const float* __restrict__ aw2,
    float* __restrict__ logits)
{
    __shared__ uint32_t Ah[128 * AST];
    __shared__ uint32_t Al[128 * AST];
    __shared__ uint32_t Bh[128 * BST];
    __shared__ uint32_t Bl[128 * BST];
    __shared__ float b1s[128];
    __shared__ float w2s[128];

    int tid = threadIdx.x;
    int wid = tid >> 5;
    int lane = tid & 31;
    int warpM = wid >> 1;          // 0..3
    int warpN = wid & 1;           // 0..1
    int rowBase = blockIdx.y * 128;
    int colBase = blockIdx.x * 128;
    int head = (MODE == 1) ? blockIdx.z : 0;
    if (MODE == 1) bOff += head * 16384;
    const uint32_t* wbh = g_wbh + bOff;
    const uint32_t* wbl = g_wbl + bOff;

    if (MODE == 1 && tid < 128) {
        b1s[tid] = ab1[head * AA + tid];
        w2s[tid] = aw2[head * AA + tid];
    }

    float acc[2][8][4];
#pragma unroll
    for (int mt = 0; mt < 2; mt++)
#pragma unroll
        for (int nt = 0; nt < 8; nt++)
#pragma unroll
            for (int r = 0; r < 4; r++) acc[mt][nt][r] = 0.f;

    for (int k0 = 0; k0 < K; k0 += 32) {
        int kp0 = k0 >> 1;
        // ---- stage A (128x32 fp32 -> packed bf16 hi/lo) ----
#pragma unroll
        for (int i = 0; i < 4; i++) {
            int f4id = tid + 256 * i;          // 0..1023
            int row = f4id >> 3;
            int kc = (f4id & 7) << 2;
            int grow = rowBase + row;
            float4 v = make_float4(0, 0, 0, 0);
            if (grow < M) v = *(const float4*)(A + (size_t)grow * K + k0 + kc);
            uint32_t h01, l01, h23, l23;
            split2(v.x, v.y, h01, l01);
            split2(v.z, v.w, h23, l23);
            int w = row * AST + (kc >> 1);
            Ah[w] = h01; Ah[w + 1] = h23;
            Al[w] = l01; Al[w + 1] = l23;
        }
        // ---- stage B: pure copy of pre-split words ----
#pragma unroll
        for (int i = 0; i < 2; i++) {
            int idx = tid + 256 * i;           // 0..511
            int row = idx >> 2;                // 0..127
            int q = (idx & 3) << 2;            // 0,4,8,12
            size_t src = (size_t)(colBase + row) * Kw + kp0 + q;
            *(uint4*)&Bh[row * BST + q] = *(const uint4*)(wbh + src);
            *(uint4*)&Bl[row * BST + q] = *(const uint4*)(wbl + src);
        }
        __syncthreads();

#pragma unroll
        for (int ks = 0; ks < 2; ks++) {
            int kw = ks * 8;
            uint32_t Af_h[2][4], Af_l[2][4];
#pragma unroll
            for (int mt = 0; mt < 2; mt++) {
                int mrow = warpM * 32 + mt * 16 + (lane >> 2);
                int base = mrow * AST + kw + (lane & 3);
                Af_h[mt][0] = Ah[base];
                Af_h[mt][1] = Ah[base + 8 * AST];
                Af_h[mt][2] = Ah[base + 4];
                Af_h[mt][3] = Ah[base + 8 * AST + 4];
                Af_l[mt][0] = Al[base];
                Af_l[mt][1] = Al[base + 8 * AST];
                Af_l[mt][2] = Al[base + 4];
                Af_l[mt][3] = Al[base + 8 * AST + 4];
            }
#pragma unroll
            for (int hf = 0; hf < 2; hf++) {
                uint32_t Bf_h[4][2], Bf_l[4][2];
#pragma unroll
                for (int nt4 = 0; nt4 < 4; nt4++) {
                    int n = warpN * 64 + hf * 32 + nt4 * 8 + (lane >> 2);
                    int bb = n * BST + kw + (lane & 3);
                    Bf_h[nt4][0] = Bh[bb];
                    Bf_h[nt4][1] = Bh[bb + 4];
                    Bf_l[nt4][0] = Bl[bb];
                    Bf_l[nt4][1] = Bl[bb + 4];
                }
#pragma unroll
                for (int mt = 0; mt < 2; mt++)
#pragma unroll
                    for (int nt4 = 0; nt4 < 4; nt4++) {
                        float* a = acc[mt][hf * 4 + nt4];
                        mma16(a, Af_h[mt], Bf_h[nt4]);
                        mma16(a, Af_h[mt], Bf_l[nt4]);
                        mma16(a, Af_l[mt], Bf_h[nt4]);
                    }
            }
        }
        __syncthreads();
    }

    if (MODE == 0) {
#pragma unroll
        for (int mt = 0; mt < 2; mt++) {
            int rg = rowBase + warpM * 32 + mt * 16 + (lane >> 2);
#pragma unroll
            for (int nt = 0; nt < 8; nt++) {
                int cg = colBase + warpN * 64 + nt * 8 + 2 * (lane & 3);
                float b0 = bias[cg], b1 = bias[cg + 1];
                if (rg < M) {
                    *(float2*)(C + (size_t)rg * N + cg) =
                        make_float2(acc[mt][nt][0] + b0, acc[mt][nt][1] + b1);
                }
                if (rg + 8 < M) {
                    *(float2*)(C + (size_t)(rg + 8) * N + cg) =
                        make_float2(acc[mt][nt][2] + b0, acc[mt][nt][3] + b1);
                }
            }
        }
    } else {
        // single column tile covers all 128 attention cols; combine warpN halves in smem
        float* sred = (float*)Ah;
        if (tid < 128) sred[tid] = 0.f;
        __syncthreads();
#pragma unroll
        for (int mt = 0; mt < 2; mt++) {
            float s0 = 0.f, s1 = 0.f;
#pragma unroll
            for (int nt = 0; nt < 8; nt++) {
                int cl = warpN * 64 + nt * 8 + 2 * (lane & 3);
                float bb0 = b1s[cl], bb1 = b1s[cl + 1];
                float ww0 = w2s[cl], ww1 = w2s[cl + 1];
                s0 += tanhf(acc[mt][nt][0] + bb0) * ww0 + tanhf(acc[mt][nt][1] + bb1) * ww1;
                s1 += tanhf(acc[mt][nt][2] + bb0) * ww0 + tanhf(acc[mt][nt][3] + bb1) * ww1;
            }
            s0 += __shfl_xor_sync(0xffffffffu, s0, 1);
            s0 += __shfl_xor_sync(0xffffffffu, s0, 2);
            s1 += __shfl_xor_sync(0xffffffffu, s1, 1);
            s1 += __shfl_xor_sync(0xffffffffu, s1, 2);
            if ((lane & 3) == 0) {
                int rl = warpM * 32 + mt * 16 + (lane >> 2);
                atomicAdd(&sred[rl], s0);
                atomicAdd(&sred[rl + 8], s1);
            }
        }
        __syncthreads();
        if (tid < 128) {
            int row = rowBase + tid;
            if (row < NN) logits[head * NN + row] = sred[tid];
        }
    }
}

// ---------------- LayerNorm (+relu, + optional residual), warp per row ----------------
__global__ __launch_bounds__(256) void ln_relu_kernel(
    const float* __restrict__ in, const float* __restrict__ gamma,
    const float* __restrict__ beta, const float* __restrict__ resid,
    float* __restrict__ outp)
{
    int gtid = blockIdx.x * blockDim.x + threadIdx.x;
    int row = gtid >> 5;
    int lane = gtid & 31;
    if (row >= NN) return;
    const float* r = in + (size_t)row * HH;
    float v[8];
    float s = 0.f, sq = 0.f;
#pragma unroll
    for (int j = 0; j < 8; j++) {
        float x = r[lane + 32 * j];
        v[j] = x;
        s += x;
        sq += x * x;
    }
#pragma unroll
    for (int off = 16; off; off >>= 1) {
        s  += __shfl_xor_sync(0xffffffffu, s, off);
        sq += __shfl_xor_sync(0xffffffffu, sq, off);
    }
    float mean = s * (1.f / HH);
    float var  = sq * (1.f / HH) - mean * mean;
    float rstd = rsqrtf(var + 1e-5f);
    float* o = outp + (size_t)row * HH;
    const float* rr = resid ? resid + (size_t)row * HH : nullptr;
#pragma unroll
    for (int j = 0; j < 8; j++) {
        int c = lane + 32 * j;
        float y = (v[j] - mean) * rstd * gamma[c] + beta[c];
        y = fmaxf(y, 0.f);
        if (rr) y += rr[c];
        o[c] = y;
    }
}

// ---------------- softmax stats: one block per head ----------------
__global__ __launch_bounds__(1024) void softmax_stats_kernel() {
    int k = blockIdx.x;
    const float* l = g_logits + k * NN;
    __shared__ float red[1024];
    int tid = threadIdx.x;
    float mx = -1e30f;
    for (int i = tid; i < NN; i += 1024) mx = fmaxf(mx, l[i]);
    red[tid] = mx;
    __syncthreads();
    for (int off = 512; off; off >>= 1) {
        if (tid < off) red[tid] = fmaxf(red[tid], red[tid + off]);
        __syncthreads();
    }
    mx = red[0];
    __syncthreads();
    float s = 0.f;
    for (int i = tid; i < NN; i += 1024) s += expf(l[i] - mx);
    red[tid] = s;
    __syncthreads();
    for (int off = 512; off; off >>= 1) {
        if (tid < off) red[tid] += red[tid + off];
        __syncthreads();
    }
    if (tid == 0) {
        g_smax[k]  = mx;
        g_srsum[k] = 1.f / red[0];
    }
}

// ---------------- pooling: write attn output + accumulate z ----------------
__global__ __launch_bounds__(256) void pool_kernel(const float* __restrict__ h, float* __restrict__ out) {
    __shared__ float a_s[256 * 4];
    int tid = threadIdx.x;
    int n0 = blockIdx.x * 256;
    int n = n0 + tid;
#pragma unroll
    for (int k = 0; k < AHD; k++) {
        float a = 0.f;
        if (n < NN) {
            a = expf(g_logits[k * NN + n] - g_smax[k]) * g_srsum[k];
            out[7 + (size_t)n * AHD + k] = a;
        }
        a_s[tid * 4 + k] = a;
    }
    __syncthreads();
    float zr[4] = {0.f, 0.f, 0.f, 0.f};
    int nmax = min(256, NN - n0);
    for (int i = 0; i < nmax; i++) {
        float hv = h[(size_t)(n0 + i) * HH + tid];
        float4 av = *(float4*)&a_s[i * 4];
        zr[0] += av.x * hv;
        zr[1] += av.y * hv;
        zr[2] += av.z * hv;
        zr[3] += av.w * hv;
    }
#pragma unroll
    for (int k = 0; k < AHD; k++) atomicAdd(&g_z[k * HH + tid], zr[k]);
}

// ---------------- classifier: single block ----------------
__global__ __launch_bounds__(256) void classifier_kernel(
    const float* __restrict__ Wc1, const float* __restrict__ bc1,
    const float* __restrict__ g1,  const float* __restrict__ b1,
    const float* __restrict__ Wc2, const float* __restrict__ bc2,
    const float* __restrict__ g2,  const float* __restrict__ b2,
    const float* __restrict__ Wc3, const float* __restrict__ bc3,
    float* __restrict__ out)
{
    __shared__ float sh[256];
    __shared__ float redA[256];
    __shared__ float redB[256];
    int tid = threadIdx.x;
    float za = 0.25f * (g_z[tid] + g_z[256 + tid] + g_z[512 + tid] + g_z[768 + tid]);
    sh[tid] = za;
    __syncthreads();

    float c = 0.f;
    if (tid < 128) {
        for (int d = 0; d < 256; d++) c += sh[d] * Wc1[d * 128 + tid];
        c += bc1[tid];
    }
    redA[tid] = (tid < 128) ? c : 0.f;
    redB[tid] = (tid < 128) ? c * c : 0.f;
    __syncthreads();
    for (int off = 128; off; off >>= 1) {
        if (tid < off) { redA[tid] += redA[tid + off]; redB[tid] += redB[tid + off]; }
        __syncthreads();
    }
    float mean = redA[0] / 128.f;
    float var  = redB[0] / 128.f - mean * mean;
    float rstd = rsqrtf(var + 1e-5f);
    __syncthreads();
    if (tid < 128) sh[tid] = fmaxf((c - mean) * rstd * g1[tid] + b1[tid], 0.f);
    __syncthreads();

    float c2 = 0.f;
    if (tid < 64) {
        for (int d = 0; d < 128; d++) c2 += sh[d] * Wc2[d * 64 + tid];
        c2 += bc2[tid];
    }
    redA[tid] = (tid < 64) ? c2 : 0.f;
    redB[tid] = (tid < 64) ? c2 * c2 : 0.f;
    __syncthreads();
    for (int off = 128; off; off >>= 1) {
        if (tid < off) { redA[tid] += redA[tid + off]; redB[tid] += redB[tid + off]; }
        __syncthreads();
    }
    mean = redA[0] / 64.f;
    var  = redB[0] / 64.f - mean * mean;
    rstd = rsqrtf(var + 1e-5f);
    __syncthreads();
    if (tid < 64) sh[tid] = fmaxf((c2 - mean) * rstd * g2[tid] + b2[tid], 0.f);
    __syncthreads();

    if (tid < NCLS) {
        float lg = 0.f;
        for (int d = 0; d < 64; d++) lg += sh[d] * Wc3[d * NCLS + tid];
        redA[tid] = lg + bc3[tid];
    }
    __syncthreads();
    if (tid == 0) {
        float mx = -1e30f;
        for (int i = 0; i < NCLS; i++) mx = fmaxf(mx, redA[i]);
        float s = 0.f;
        for (int i = 0; i < NCLS; i++) s += expf(redA[i] - mx);
        float rs = 1.f / s;
        for (int i = 0; i < NCLS; i++) out[i] = expf(redA[i] - mx) * rs;
    }
}

// ---------------- launcher ----------------
extern "C" void kernel_launch(void* const* d_in, const int* in_sizes, int n_in,
                              void* d_out, int out_size)
{
    const float* x     = (const float*)d_in[0];
    const int*   ei    = (const int*)  d_in[1];
    const float* W_in  = (const float*)d_in[2];
    const float* b_in  = (const float*)d_in[3];
    const float* gW1   = (const float*)d_in[4];
    const float* gb1   = (const float*)d_in[5];
    const float* glng  = (const float*)d_in[6];
    const float* glnb  = (const float*)d_in[7];
    const float* gW2   = (const float*)d_in[8];
    const float* gb2   = (const float*)d_in[9];
    const float* eps   = (const float*)d_in[10];
    const float* lng   = (const float*)d_in[11];
    const float* lnb   = (const float*)d_in[12];
    const float* aW1   = (const float*)d_in[13];
    const float* ab1   = (const float*)d_in[14];
    const float* aW2   = (const float*)d_in[15];
    const float* Wc1   = (const float*)d_in[17];
    const float* bc1   = (const float*)d_in[18];
    const float* lc1g  = (const float*)d_in[19];
    const float* lc1b  = (const float*)d_in[20];
    const float* Wc2   = (const float*)d_in[21];
    const float* bc2   = (const float*)d_in[22];
    const float* lc2g  = (const float*)d_in[23];
    const float* lc2b  = (const float*)d_in[24];
    const float* Wc3   = (const float*)d_in[25];
    const float* bc3   = (const float*)d_in[26];
    float* out = (float*)d_out;

    float *p_h, *p_agg, *p_t, *p_logits;
    cudaGetSymbolAddress((void**)&p_h, g_h);
    cudaGetSymbolAddress((void**)&p_agg, g_agg);
    cudaGetSymbolAddress((void**)&p_t, g_t);
    cudaGetSymbolAddress((void**)&p_logits, g_logits);

    const int MB = (NN + 127) / 128;               // 391 row tiles
    const int WARP_BLKS = (NN * 32 + 255) / 256;   // 6250
    const int ROW_BLKS  = (NN + 7) / 8;            // 6250
    const int EDGE_BLKS = (EE + 255) / 256;        // 3125
    const int POOL_BLKS = (NN + 255) / 256;        // 196
    const int WS_BLKS   = (WSPLIT_TOTAL + 255) / 256;

    // weight pre-split + CSR build + scratch zero
    wsplit_kernel<<<WS_BLKS, 256>>>(W_in, gW1, gW2, aW1);
    zero_kernel<<<POOL_BLKS, 256>>>();
    hist_kernel<<<EDGE_BLKS, 256>>>(ei);
    scan_kernel<<<1, 1024>>>();
    fill_kernel<<<EDGE_BLKS, 256>>>(ei);

    // input projection: h = x @ W_in + b_in
    gemm_bf16_kernel<0><<<dim3(HH / 128, MB), 256>>>(
        x, OFF_WIN, FF / 2, b_in, p_h, NN, HH, FF, nullptr, nullptr, nullptr);

    // GIN layers
    for (int l = 0; l < 2; l++) {
        gin_agg_kernel<<<WARP_BLKS, 256>>>(eps, l);
        gemm_bf16_kernel<0><<<dim3(HH / 128, MB), 256>>>(
            p_agg, OFF_GW1 + l * 32768, HH / 2, gb1 + l * HH, p_t,
            NN, HH, HH, nullptr, nullptr, nullptr);
        ln_relu_kernel<<<ROW_BLKS, 256>>>(p_t, glng + l * HH, glnb + l * HH, nullptr, p_t);
        gemm_bf16_kernel<0><<<dim3(HH / 128, MB), 256>>>(
            p_t, OFF_GW2 + l * 32768, HH / 2, gb2 + l * HH, p_agg,
            NN, HH, HH, nullptr, nullptr, nullptr);
        ln_relu_kernel<<<ROW_BLKS, 256>>>(p_agg, lng + l * HH, lnb + l * HH, p_h, p_h);
    }

    // attention logits: single col tile, direct store (b2 softmax-invariant)
    gemm_bf16_kernel<1><<<dim3(1, MB, AHD), 256>>>(
        p_h, OFF_AW1, AA, nullptr, nullptr, NN, AA, HH, ab1, aW2, p_logits);

    softmax_stats_kernel<<<AHD, 1024>>>();
    pool_kernel<<<POOL_BLKS, 256>>>(p_h, out);

    // classifier head
    classifier_kernel<<<1, 256>>>(Wc1, bc1, lc1g, lc1b, Wc2, bc2, lc2g, lc2b, Wc3, bc3, out);
}

// round 16
// speedup vs baseline: 1.3562x; 1.3562x over previous
#include <cuda_runtime.h>
#include <cuda_bf16.h>
#include <math.h>
#include <stdint.h>

#define NN   50000
#define EE   800000
#define FF   768
#define HH   256
#define AA   128
#define AHD  4
#define NCLS 7

// pre-split weight buffer offsets (uint32 words)
#define OFF_WIN 0
#define OFF_GW1 98304
#define OFF_GW2 163840
#define OFF_AW1 229376
#define WSPLIT_TOTAL 294912

#define SCAN_NB 49   // ceil(50000/1024)

// ---------------- scratch (no allocations allowed) ----------------
__device__ __align__(16) float g_h[(size_t)NN * HH];
__device__ __align__(16) float g_agg[(size_t)NN * HH];
__device__ __align__(16) float g_t[(size_t)NN * HH];
__device__ __align__(16) uint32_t g_wbh[WSPLIT_TOTAL];
__device__ __align__(16) uint32_t g_wbl[WSPLIT_TOTAL];
__device__ int   g_deg[NN];
__device__ int   g_rowstart[NN + 1];
__device__ int   g_cursor[NN];
__device__ int   g_srclist[EE];
__device__ int   g_bsum[SCAN_NB];
__device__ int   g_boff[SCAN_NB];
__device__ float g_logits[AHD * NN];
__device__ float g_smax[AHD];
__device__ float g_srsum[AHD];
__device__ float g_z[AHD * HH];

// ---------------- bf16 split helper ----------------
__device__ __forceinline__ void split2(float x, float y, uint32_t& hi, uint32_t& lo) {
    __nv_bfloat16 hx = __float2bfloat16(x), hy = __float2bfloat16(y);
    float rx = x - __bfloat162float(hx), ry = y - __bfloat162float(hy);
    __nv_bfloat16 lx = __float2bfloat16(rx), ly = __float2bfloat16(ry);
    hi = (uint32_t)(*(unsigned short*)&hx) | ((uint32_t)(*(unsigned short*)&hy) << 16);
    lo = (uint32_t)(*(unsigned short*)&lx) | ((uint32_t)(*(unsigned short*)&ly) << 16);
}

// ---------------- weight pre-split: [K][N] fp32 -> [N][K/2] packed hi/lo ----------------
__global__ void wsplit_kernel(const float* __restrict__ W_in, const float* __restrict__ gW1,
                              const float* __restrict__ gW2, const float* __restrict__ aW1) {
    int idx = blockIdx.x * blockDim.x + threadIdx.x;
    if (idx >= WSPLIT_TOTAL) return;
    const float* B;
    int N, Kw, dstOff, local;
    if (idx < OFF_GW1) {
        B = W_in; N = 256; Kw = 384; dstOff = OFF_WIN; local = idx;
    } else if (idx < OFF_GW2) {
        int t = idx - OFF_GW1;
        int l = t >> 15;
        local = t & 32767;
        B = gW1 + l * 65536; N = 256; Kw = 128; dstOff = OFF_GW1 + l * 32768;
    } else if (idx < OFF_AW1) {
        int t = idx - OFF_GW2;
        int l = t >> 15;
        local = t & 32767;
        B = gW2 + l * 65536; N = 256; Kw = 128; dstOff = OFF_GW2 + l * 32768;
    } else {
        int t = idx - OFF_AW1;
        int h = t >> 14;
        local = t & 16383;
        B = aW1 + h * 32768; N = 128; Kw = 128; dstOff = OFF_AW1 + h * 16384;
    }
    int kp = local / N, n = local - kp * N;
    float v0 = B[(size_t)(2 * kp) * N + n];
    float v1 = B[(size_t)(2 * kp + 1) * N + n];
    uint32_t hi, lo;
    split2(v0, v1, hi, lo);
    g_wbh[dstOff + n * Kw + kp] = hi;
    g_wbl[dstOff + n * Kw + kp] = lo;
}

// ---------------- small utility kernels ----------------
__global__ void zero_kernel() {
    int i = blockIdx.x * blockDim.x + threadIdx.x;
    if (i < NN) g_deg[i] = 0;
    if (i < AHD * HH) g_z[i] = 0.f;
    if (i < AHD * NN) g_logits[i] = 0.f;
    if (i == 0) g_rowstart[NN] = EE;
}

__global__ void hist_kernel(const int* __restrict__ ei) {
    int e = blockIdx.x * blockDim.x + threadIdx.x;
    if (e < EE) atomicAdd(&g_deg[ei[EE + e]], 1);
}

// ---------------- 3-phase multi-block exclusive scan over g_deg ----------------
__global__ __launch_bounds__(256) void scan_p1() {
    __shared__ int warpsum[8];
    int b = blockIdx.x, tid = threadIdx.x;
    int base = b * 1024 + tid * 4;
    int s = 0;
#pragma unroll
    for (int j = 0; j < 4; j++) {
        int idx = base + j;
        if (idx < NN) s += g_deg[idx];
    }
#pragma unroll
    for (int off = 16; off; off >>= 1) s += __shfl_xor_sync(0xffffffffu, s, off);
    if ((tid & 31) == 0) warpsum[tid >> 5] = s;
    __syncthreads();
    if (tid == 0) {
        int t = 0;
#pragma unroll
        for (int w = 0; w < 8; w++) t += warpsum[w];
        g_bsum[b] = t;
    }
}

__global__ __launch_bounds__(64) void scan_p2() {
    __shared__ int sh[SCAN_NB];
    int tid = threadIdx.x;
    if (tid < SCAN_NB) sh[tid] = g_bsum[tid];
    __syncthreads();
    if (tid == 0) {
        int run = 0;
        for (int i = 0; i < SCAN_NB; i++) {
            g_boff[i] = run;
            run += sh[i];
        }
    }
}

__global__ __launch_bounds__(256) void scan_p3() {
    __shared__ int tsum[256];
    int b = blockIdx.x, tid = threadIdx.x;
    int base = b * 1024 + tid * 4;
    int v[4];
    int s = 0;
#pragma unroll
    for (int j = 0; j < 4; j++) {
        int idx = base + j;
        v[j] = (idx < NN) ? g_deg[idx] : 0;
        s += v[j];
    }
    tsum[tid] = s;
    __syncthreads();
    // block exclusive scan of thread sums
    for (int off = 1; off < 256; off <<= 1) {
        int t = 0;
        if (tid >= off) t = tsum[tid - off];
        __syncthreads();
        tsum[tid] += t;
        __syncthreads();
    }
    int run = g_boff[b] + ((tid == 0) ? 0 : tsum[tid - 1]);
#pragma unroll
    for (int j = 0; j < 4; j++) {
        int idx = base + j;
        if (idx < NN) {
            g_rowstart[idx] = run;
            g_cursor[idx] = run;
            run += v[j];
        }
    }
}

__global__ void fill_kernel(const int* __restrict__ ei) {
    int e = blockIdx.x * blockDim.x + threadIdx.x;
    if (e < EE) {
        int d = ei[EE + e];
        int pos = atomicAdd(&g_cursor[d], 1);
        g_srclist[pos] = ei[e];
    }
}

// ---------------- GIN aggregation: one warp per destination node ----------------
__device__ __forceinline__ float4 f4add(float4 a, float4 b) {
    return make_float4(a.x + b.x, a.y + b.y, a.z + b.z, a.w + b.w);
}

__global__ __launch_bounds__(256) void gin_agg_kernel(const float* __restrict__ epsv, int layer) {
    int gtid = blockIdx.x * blockDim.x + threadIdx.x;
    int node = gtid >> 5;
    int lane = gtid & 31;
    if (node >= NN) return;
    int s = g_rowstart[node];
    int e = g_rowstart[node + 1];
    float4 acc0 = make_float4(0, 0, 0, 0);
    float4 acc1 = make_float4(0, 0, 0, 0);
    for (int i = s; i < e; i++) {
        int src = g_srclist[i];
        const float4* r = (const float4*)(g_h + (size_t)src * HH);
        acc0 = f4add(acc0, r[lane]);
        acc1 = f4add(acc1, r[lane + 32]);
    }
    float ep = 1.f + epsv[layer];
    const float4* hr = (const float4*)(g_h + (size_t)node * HH);
    float4 h0 = hr[lane], h1 = hr[lane + 32];
    float4* ar = (float4*)(g_agg + (size_t)node * HH);
    ar[lane]      = make_float4(ep * h0.x + acc0.x, ep * h0.y + acc0.y, ep * h0.z + acc0.z, ep * h0.w + acc0.w);
    ar[lane + 32] = make_float4(ep * h1.x + acc1.x, ep * h1.y + acc1.y, ep * h1.z + acc1.z, ep * h1.w + acc1.w);
}

// ---------------- split-bf16 tensor-core GEMM, 128x64 tile (R14 config) ----------------
// B pre-split/transposed in g_wbh/g_wbl at word offset bOff, row stride Kw words.
// MODE 0: C = A@B + bias
// MODE 1: attention epilogue -> logits[head][row] += sum_col tanh(acc + b1)*w2

__device__ __forceinline__ void mma16(float* d, const uint32_t* a, const uint32_t* b) {
    asm volatile(
        "mma.sync.aligned.m16n8k16.row.col.f32.bf16.bf16.f32 "
        "{%0,%1,%2,%3}, {%4,%5,%6,%7}, {%8,%9}, {%0,%1,%2,%3};"
        : "+f"(d[0]), "+f"(d[1]), "+f"(d[2]), "+f"(d[3])
        : "r"(a[0]), "r"(a[1]), "r"(a[2]), "r"(a[3]), "r"(b[0]), "r"(b[1]));
}

#define AST 17
#define BST 20

template <int MODE>
__global__ __launch_bounds__(256, 2) void gemm_bf16_kernel(
    const float* __restrict__ A, int bOff, int Kw,
    const float* __restrict__ bias, float* __restrict__ C,
    int M, int N, int K,
    const float* __restrict__ ab1, const float* __restrict__ aw2,
    float* __restrict__ logits)
{
    __shared__ uint32_t Ah[128 * AST];
    __shared__ uint32_t Al[128 * AST];
    __shared__ uint32_t Bh[64 * BST];
    __shared__ uint32_t Bl[64 * BST];

    int tid = threadIdx.x;
    int wid = tid >> 5;
    int lane = tid & 31;
    int warpM = wid >> 1;          // 0..3 (32 rows each)
    int warpN = wid & 1;           // 0..1 (32 cols each)
    int rowBase = blockIdx.y * 128;
    int colBase = blockIdx.x * 64;
    int head = (MODE == 1) ? blockIdx.z : 0;
    if (MODE == 1) bOff += head * 16384;
    const uint32_t* wbh = g_wbh + bOff;
    const uint32_t* wbl = g_wbl + bOff;

    float acc[2][4][4];
#pragma unroll
    for (int mt = 0; mt < 2; mt++)
#pragma unroll
        for (int nt = 0; nt < 4; nt++)
#pragma unroll
            for (int r = 0; r < 4; r++) acc[mt][nt][r] = 0.f;

    for (int k0 = 0; k0 < K; k0 += 32) {
        int kp0 = k0 >> 1;
        // ---- stage A (128x32 fp32 -> packed bf16 hi/lo) ----
#pragma unroll
        for (int i = 0; i < 4; i++) {
            int f4id = tid + 256 * i;          // 0..1023
            int row = f4id >> 3;
            int kc = (f4id & 7) << 2;
            int grow = rowBase + row;
            float4 v = make_float4(0, 0, 0, 0);
            if (grow < M) v = *(const float4*)(A + (size_t)grow * K + k0 + kc);
            uint32_t h01, l01, h23, l23;
            split2(v.x, v.y, h01, l01);
            split2(v.z, v.w, h23, l23);
            int w = row * AST + (kc >> 1);
            Ah[w] = h01; Ah[w + 1] = h23;
            Al[w] = l01; Al[w + 1] = l23;
        }
        // ---- stage B: pure uint4 copy of pre-split words (64 rows x 16 words) ----
        {
            int row = tid >> 2;                // 0..63
            int q = (tid & 3) << 2;            // 0,4,8,12
            size_t src = (size_t)(colBase + row) * Kw + kp0 + q;
            *(uint4*)&Bh[row * BST + q] = *(const uint4*)(wbh + src);
            *(uint4*)&Bl[row * BST + q] = *(const uint4*)(wbl + src);
        }
        __syncthreads();

#pragma unroll
        for (int ks = 0; ks < 2; ks++) {
            int kw = ks * 8;
            uint32_t Af_h[2][4], Af_l[2][4];
#pragma unroll
            for (int mt = 0; mt < 2; mt++) {
                int mrow = warpM * 32 + mt * 16 + (lane >> 2);
                int base = mrow * AST + kw + (lane & 3);
                Af_h[mt][0] = Ah[base];
                Af_h[mt][1] = Ah[base + 8 * AST];
                Af_h[mt][2] = Ah[base + 4];
                Af_h[mt][3] = Ah[base + 8 * AST + 4];
                Af_l[mt][0] = Al[base];
                Af_l[mt][1] = Al[base + 8 * AST];
                Af_l[mt][2] = Al[base + 4];
                Af_l[mt][3] = Al[base + 8 * AST + 4];
            }
            uint32_t Bf_h[4][2], Bf_l[4][2];
#pragma unroll
            for (int nt = 0; nt < 4; nt++) {
                int n = warpN * 32 + nt * 8 + (lane >> 2);
                int bb = n * BST + kw + (lane & 3);
                Bf_h[nt][0] = Bh[bb];
                Bf_h[nt][1] = Bh[bb + 4];
                Bf_l[nt][0] = Bl[bb];
                Bf_l[nt][1] = Bl[bb + 4];
            }
#pragma unroll
            for (int mt = 0; mt < 2; mt++)
#pragma unroll
                for (int nt = 0; nt < 4; nt++) {
                    mma16(acc[mt][nt], Af_h[mt], Bf_h[nt]);
                    mma16(acc[mt][nt], Af_h[mt], Bf_l[nt]);
                    mma16(acc[mt][nt], Af_l[mt], Bf_h[nt]);
                }
        }
        __syncthreads();
    }

    if (MODE == 0) {
#pragma unroll
        for (int mt = 0; mt < 2; mt++) {
            int rg = rowBase + warpM * 32 + mt * 16 + (lane >> 2);
#pragma unroll
            for (int nt = 0; nt < 4; nt++) {
                int cg = colBase + warpN * 32 + nt * 8 + 2 * (lane & 3);
                float b0 = bias[cg], b1 = bias[cg + 1];
                if (rg < M) {
                    *(float2*)(C + (size_t)rg * N + cg) =
                        make_float2(acc[mt][nt][0] + b0, acc[mt][nt][1] + b1);
                }
                if (rg + 8 < M) {
                    *(float2*)(C + (size_t)(rg + 8) * N + cg) =
                        make_float2(acc[mt][nt][2] + b0, acc[mt][nt][3] + b1);
                }
            }
        }
    } else {
        const float* b1p = ab1 + head * AA;
        const float* w2p = aw2 + head * AA;
#pragma unroll
        for (int mt = 0; mt < 2; mt++) {
            float s0 = 0.f, s1 = 0.f;
#pragma unroll
            for (int nt = 0; nt < 4; nt++) {
                int cl = colBase + warpN * 32 + nt * 8 + 2 * (lane & 3);
                float bb0 = b1p[cl], bb1 = b1p[cl + 1];
                float ww0 = w2p[cl], ww1 = w2p[cl + 1];
                s0 += tanhf(acc[mt][nt][0] + bb0) * ww0 + tanhf(acc[mt][nt][1] + bb1) * ww1;
                s1 += tanhf(acc[mt][nt][2] + bb0) * ww0 + tanhf(acc[mt][nt][3] + bb1) * ww1;
            }
            s0 += __shfl_xor_sync(0xffffffffu, s0, 1);
            s0 += __shfl_xor_sync(0xffffffffu, s0, 2);
            s1 += __shfl_xor_sync(0xffffffffu, s1, 1);
            s1 += __shfl_xor_sync(0xffffffffu, s1, 2);
            if ((lane & 3) == 0) {
                int rg = rowBase + warpM * 32 + mt * 16 + (lane >> 2);
                if (rg < M)     atomicAdd(&logits[head * NN + rg], s0);
                if (rg + 8 < M) atomicAdd(&logits[head * NN + rg + 8], s1);
            }
        }
    }
}

// ---------------- LayerNorm (+relu, + optional residual), warp per row ----------------
__global__ __launch_bounds__(256) void ln_relu_kernel(
    const float* __restrict__ in, const float* __restrict__ gamma,
    const float* __restrict__ beta, const float* __restrict__ resid,
    float* __restrict__ outp)
{
    int gtid = blockIdx.x * blockDim.x + threadIdx.x;
    int row = gtid >> 5;
    int lane = gtid & 31;
    if (row >= NN) return;
    const float* r = in + (size_t)row * HH;
    float v[8];
    float s = 0.f, sq = 0.f;
#pragma unroll
    for (int j = 0; j < 8; j++) {
        float x = r[lane + 32 * j];
        v[j] = x;
        s += x;
        sq += x * x;
    }
#pragma unroll
    for (int off = 16; off; off >>= 1) {
        s  += __shfl_xor_sync(0xffffffffu, s, off);
        sq += __shfl_xor_sync(0xffffffffu, sq, off);
    }
    float mean = s * (1.f / HH);
    float var  = sq * (1.f / HH) - mean * mean;
    float rstd = rsqrtf(var + 1e-5f);
    float* o = outp + (size_t)row * HH;
    const float* rr = resid ? resid + (size_t)row * HH : nullptr;
#pragma unroll
    for (int j = 0; j < 8; j++) {
        int c = lane + 32 * j;
        float y = (v[j] - mean) * rstd * gamma[c] + beta[c];
        y = fmaxf(y, 0.f);
        if (rr) y += rr[c];
        o[c] = y;
    }
}

// ---------------- softmax stats: one block per head ----------------
__global__ __launch_bounds__(1024) void softmax_stats_kernel() {
    int k = blockIdx.x;
    const float* l = g_logits + k * NN;
    __shared__ float red[1024];
    int tid = threadIdx.x;
    float mx = -1e30f;
    for (int i = tid; i < NN; i += 1024) mx = fmaxf(mx, l[i]);
    red[tid] = mx;
    __syncthreads();
    for (int off = 512; off; off >>= 1) {
        if (tid < off) red[tid] = fmaxf(red[tid], red[tid + off]);
        __syncthreads();
    }
    mx = red[0];
    __syncthreads();
    float s = 0.f;
    for (int i = tid; i < NN; i += 1024) s += expf(l[i] - mx);
    red[tid] = s;
    __syncthreads();
    for (int off = 512; off; off >>= 1) {
        if (tid < off) red[tid] += red[tid + off];
        __syncthreads();
    }
    if (tid == 0) {
        g_smax[k]  = mx;
        g_srsum[k] = 1.f / red[0];
    }
}

// ---------------- pooling: write attn output + accumulate z ----------------
__global__ __launch_bounds__(256) void pool_kernel(const float* __restrict__ h, float* __restrict__ out) {
    __shared__ float a_s[256 * 4];
    int tid = threadIdx.x;
    int n0 = blockIdx.x * 256;
    int n = n0 + tid;
#pragma unroll
    for (int k = 0; k < AHD; k++) {
        float a = 0.f;
        if (n < NN) {
            a = expf(g_logits[k * NN + n] - g_smax[k]) * g_srsum[k];
            out[7 + (size_t)n * AHD + k] = a;
        }
        a_s[tid * 4 + k] = a;
    }
    __syncthreads();
    float zr[4] = {0.f, 0.f, 0.f, 0.f};
    int nmax = min(256, NN - n0);
    for (int i = 0; i < nmax; i++) {
        float hv = h[(size_t)(n0 + i) * HH + tid];
        float4 av = *(float4*)&a_s[i * 4];
        zr[0] += av.x * hv;
        zr[1] += av.y * hv;
        zr[2] += av.z * hv;
        zr[3] += av.w * hv;
    }
#pragma unroll
    for (int k = 0; k < AHD; k++) atomicAdd(&g_z[k * HH + tid], zr[k]);
}

// ---------------- classifier: single block ----------------
__global__ __launch_bounds__(256) void classifier_kernel(
    const float* __restrict__ Wc1, const float* __restrict__ bc1,
    const float* __restrict__ g1,  const float* __restrict__ b1,
    const float* __restrict__ Wc2, const float* __restrict__ bc2,
    const float* __restrict__ g2,  const float* __restrict__ b2,
    const float* __restrict__ Wc3, const float* __restrict__ bc3,
    float* __restrict__ out)
{
    __shared__ float sh[256];
    __shared__ float redA[256];
    __shared__ float redB[256];
    int tid = threadIdx.x;
    float za = 0.25f * (g_z[tid] + g_z[256 + tid] + g_z[512 + tid] + g_z[768 + tid]);
    sh[tid] = za;
    __syncthreads();

    float c = 0.f;
    if (tid < 128) {
        for (int d = 0; d < 256; d++) c += sh[d] * Wc1[d * 128 + tid];
        c += bc1[tid];
    }
    redA[tid] = (tid < 128) ? c : 0.f;
    redB[tid] = (tid < 128) ? c * c : 0.f;
    __syncthreads();
    for (int off = 128; off; off >>= 1) {
        if (tid < off) { redA[tid] += redA[tid + off]; redB[tid] += redB[tid + off]; }
        __syncthreads();
    }
    float mean = redA[0] / 128.f;
    float var  = redB[0] / 128.f - mean * mean;
    float rstd = rsqrtf(var + 1e-5f);
    __syncthreads();
    if (tid < 128) sh[tid] = fmaxf((c - mean) * rstd * g1[tid] + b1[tid], 0.f);
    __syncthreads();

    float c2 = 0.f;
    if (tid < 64) {
        for (int d = 0; d < 128; d++) c2 += sh[d] * Wc2[d * 64 + tid];
        c2 += bc2[tid];
    }
    redA[tid] = (tid < 64) ? c2 : 0.f;
    redB[tid] = (tid < 64) ? c2 * c2 : 0.f;
    __syncthreads();
    for (int off = 128; off; off >>= 1) {
        if (tid < off) { redA[tid] += redA[tid + off]; redB[tid] += redB[tid + off]; }
        __syncthreads();
    }
    mean = redA[0] / 64.f;
    var  = redB[0] / 64.f - mean * mean;
    rstd = rsqrtf(var + 1e-5f);
    __syncthreads();
    if (tid < 64) sh[tid] = fmaxf((c2 - mean) * rstd * g2[tid] + b2[tid], 0.f);
    __syncthreads();

    if (tid < NCLS) {
        float lg = 0.f;
        for (int d = 0; d < 64; d++) lg += sh[d] * Wc3[d * NCLS + tid];
        redA[tid] = lg + bc3[tid];
    }
    __syncthreads();
    if (tid == 0) {
        float mx = -1e30f;
        for (int i = 0; i < NCLS; i++) mx = fmaxf(mx, redA[i]);
        float s = 0.f;
        for (int i = 0; i < NCLS; i++) s += expf(redA[i] - mx);
        float rs = 1.f / s;
        for (int i = 0; i < NCLS; i++) out[i] = expf(redA[i] - mx) * rs;
    }
}

// ---------------- launcher ----------------
extern "C" void kernel_launch(void* const* d_in, const int* in_sizes, int n_in,
                              void* d_out, int out_size)
{
    const float* x     = (const float*)d_in[0];
    const int*   ei    = (const int*)  d_in[1];
    const float* W_in  = (const float*)d_in[2];
    const float* b_in  = (const float*)d_in[3];
    const float* gW1   = (const float*)d_in[4];
    const float* gb1   = (const float*)d_in[5];
    const float* glng  = (const float*)d_in[6];
    const float* glnb  = (const float*)d_in[7];
    const float* gW2   = (const float*)d_in[8];
    const float* gb2   = (const float*)d_in[9];
    const float* eps   = (const float*)d_in[10];
    const float* lng   = (const float*)d_in[11];
    const float* lnb   = (const float*)d_in[12];
    const float* aW1   = (const float*)d_in[13];
    const float* ab1   = (const float*)d_in[14];
    const float* aW2   = (const float*)d_in[15];
    const float* Wc1   = (const float*)d_in[17];
    const float* bc1   = (const float*)d_in[18];
    const float* lc1g  = (const float*)d_in[19];
    const float* lc1b  = (const float*)d_in[20];
    const float* Wc2   = (const float*)d_in[21];
    const float* bc2   = (const float*)d_in[22];
    const float* lc2g  = (const float*)d_in[23];
    const float* lc2b  = (const float*)d_in[24];
    const float* Wc3   = (const float*)d_in[25];
    const float* bc3   = (const float*)d_in[26];
    float* out = (float*)d_out;

    float *p_h, *p_agg, *p_t, *p_logits;
    cudaGetSymbolAddress((void**)&p_h, g_h);
    cudaGetSymbolAddress((void**)&p_agg, g_agg);
    cudaGetSymbolAddress((void**)&p_t, g_t);
    cudaGetSymbolAddress((void**)&p_logits, g_logits);

    const int MB = (NN + 127) / 128;               // 391 row tiles
    const int WARP_BLKS = (NN * 32 + 255) / 256;   // 6250
    const int ROW_BLKS  = (NN + 7) / 8;            // 6250
    const int EDGE_BLKS = (EE + 255) / 256;        // 3125
    const int POOL_BLKS = (NN + 255) / 256;        // 196
    const int ZERO_BLKS = (AHD * NN + 255) / 256;  // 782
    const int WS_BLKS   = (WSPLIT_TOTAL + 255) / 256;

    // weight pre-split + CSR build + scratch zero
    wsplit_kernel<<<WS_BLKS, 256>>>(W_in, gW1, gW2, aW1);
    zero_kernel<<<ZERO_BLKS, 256>>>();
    hist_kernel<<<EDGE_BLKS, 256>>>(ei);
    scan_p1<<<SCAN_NB, 256>>>();
    scan_p2<<<1, 64>>>();
    scan_p3<<<SCAN_NB, 256>>>();
    fill_kernel<<<EDGE_BLKS, 256>>>(ei);

    // input projection: h = x @ W_in + b_in
    gemm_bf16_kernel<0><<<dim3(HH / 64, MB), 256>>>(
        x, OFF_WIN, FF / 2, b_in, p_h, NN, HH, FF, nullptr, nullptr, nullptr);

    // GIN layers
    for (int l = 0; l < 2; l++) {
        gin_agg_kernel<<<WARP_BLKS, 256>>>(eps, l);
        gemm_bf16_kernel<0><<<dim3(HH / 64, MB), 256>>>(
            p_agg, OFF_GW1 + l * 32768, HH / 2, gb1 + l * HH, p_t,
            NN, HH, HH, nullptr, nullptr, nullptr);
        ln_relu_kernel<<<ROW_BLKS, 256>>>(p_t, glng + l * HH, glnb + l * HH, nullptr, p_t);
        gemm_bf16_kernel<0><<<dim3(HH / 64, MB), 256>>>(
            p_t, OFF_GW2 + l * 32768, HH / 2, gb2 + l * HH, p_agg,
            NN, HH, HH, nullptr, nullptr, nullptr);
        ln_relu_kernel<<<ROW_BLKS, 256>>>(p_agg, lng + l * HH, lnb + l * HH, p_h, p_h);
    }

    // attention logits: fused tanh(h@W1 + b1)·W2 partial reduce into g_logits
    gemm_bf16_kernel<1><<<dim3(AA / 64, MB, AHD), 256>>>(
        p_h, OFF_AW1, AA, nullptr, nullptr, NN, AA, HH, ab1, aW2, p_logits);

    softmax_stats_kernel<<<AHD, 1024>>>();
    pool_kernel<<<POOL_BLKS, 256>>>(p_h, out);

    // classifier head
    classifier_kernel<<<1, 256>>>(Wc1, bc1, lc1g, lc1b, Wc2, bc2, lc2g, lc2b, Wc3, bc3, out);
}

// round 17
// speedup vs baseline: 1.4376x; 1.0601x over previous
#include <cuda_runtime.h>
#include <cuda_bf16.h>
#include <math.h>
#include <stdint.h>

#define NN   50000
#define EE   800000
#define FF   768
#define HH   256
#define AA   128
#define AHD  4
#define NCLS 7

// pre-split weight buffer offsets (uint32 words)
#define OFF_WIN 0
#define OFF_GW1 98304
#define OFF_GW2 163840
#define OFF_AW1 229376
#define WSPLIT_TOTAL 294912

#define SCAN_NB 49   // ceil(50000/1024)

// ---------------- scratch (no allocations allowed) ----------------
__device__ __align__(16) float g_h[(size_t)NN * HH];
__device__ __align__(16) float g_t[(size_t)NN * HH];
__device__ __align__(16) uint32_t g_ah[(size_t)NN * (HH / 2)];   // packed bf16-hi A operand
__device__ __align__(16) uint32_t g_al[(size_t)NN * (HH / 2)];   // packed bf16-lo A operand
__device__ __align__(16) uint32_t g_wbh[WSPLIT_TOTAL];
__device__ __align__(16) uint32_t g_wbl[WSPLIT_TOTAL];
__device__ int   g_deg[NN];
__device__ int   g_rowstart[NN + 1];
__device__ int   g_cursor[NN];
__device__ int   g_srclist[EE];
__device__ int   g_bsum[SCAN_NB];
__device__ int   g_boff[SCAN_NB];
__device__ float g_logits[AHD * NN];
__device__ float g_smax[AHD];
__device__ float g_srsum[AHD];
__device__ float g_z[AHD * HH];

// ---------------- bf16 split helper ----------------
__device__ __forceinline__ void split2(float x, float y, uint32_t& hi, uint32_t& lo) {
    __nv_bfloat16 hx = __float2bfloat16(x), hy = __float2bfloat16(y);
    float rx = x - __bfloat162float(hx), ry = y - __bfloat162float(hy);
    __nv_bfloat16 lx = __float2bfloat16(rx), ly = __float2bfloat16(ry);
    hi = (uint32_t)(*(unsigned short*)&hx) | ((uint32_t)(*(unsigned short*)&hy) << 16);
    lo = (uint32_t)(*(unsigned short*)&lx) | ((uint32_t)(*(unsigned short*)&ly) << 16);
}

// ---------------- weight pre-split: [K][N] fp32 -> [N][K/2] packed hi/lo ----------------
__global__ void wsplit_kernel(const float* __restrict__ W_in, const float* __restrict__ gW1,
                              const float* __restrict__ gW2, const float* __restrict__ aW1) {
    int idx = blockIdx.x * blockDim.x + threadIdx.x;
    if (idx >= WSPLIT_TOTAL) return;
    const float* B;
    int N, Kw, dstOff, local;
    if (idx < OFF_GW1) {
        B = W_in; N = 256; Kw = 384; dstOff = OFF_WIN; local = idx;
    } else if (idx < OFF_GW2) {
        int t = idx - OFF_GW1;
        int l = t >> 15;
        local = t & 32767;
        B = gW1 + l * 65536; N = 256; Kw = 128; dstOff = OFF_GW1 + l * 32768;
    } else if (idx < OFF_AW1) {
        int t = idx - OFF_GW2;
        int l = t >> 15;
        local = t & 32767;
        B = gW2 + l * 65536; N = 256; Kw = 128; dstOff = OFF_GW2 + l * 32768;
    } else {
        int t = idx - OFF_AW1;
        int h = t >> 14;
        local = t & 16383;
        B = aW1 + h * 32768; N = 128; Kw = 128; dstOff = OFF_AW1 + h * 16384;
    }
    int kp = local / N, n = local - kp * N;
    float v0 = B[(size_t)(2 * kp) * N + n];
    float v1 = B[(size_t)(2 * kp + 1) * N + n];
    uint32_t hi, lo;
    split2(v0, v1, hi, lo);
    g_wbh[dstOff + n * Kw + kp] = hi;
    g_wbl[dstOff + n * Kw + kp] = lo;
}

// ---------------- small utility kernels ----------------
__global__ void zero_kernel() {
    int i = blockIdx.x * blockDim.x + threadIdx.x;
    if (i < NN) g_deg[i] = 0;
    if (i < AHD * HH) g_z[i] = 0.f;
    if (i < AHD * NN) g_logits[i] = 0.f;
    if (i == 0) g_rowstart[NN] = EE;
}

__global__ void hist_kernel(const int* __restrict__ ei) {
    int e = blockIdx.x * blockDim.x + threadIdx.x;
    if (e < EE) atomicAdd(&g_deg[ei[EE + e]], 1);
}

// ---------------- 3-phase multi-block exclusive scan over g_deg ----------------
__global__ __launch_bounds__(256) void scan_p1() {
    __shared__ int warpsum[8];
    int b = blockIdx.x, tid = threadIdx.x;
    int base = b * 1024 + tid * 4;
    int s = 0;
#pragma unroll
    for (int j = 0; j < 4; j++) {
        int idx = base + j;
        if (idx < NN) s += g_deg[idx];
    }
#pragma unroll
    for (int off = 16; off; off >>= 1) s += __shfl_xor_sync(0xffffffffu, s, off);
    if ((tid & 31) == 0) warpsum[tid >> 5] = s;
    __syncthreads();
    if (tid == 0) {
        int t = 0;
#pragma unroll
        for (int w = 0; w < 8; w++) t += warpsum[w];
        g_bsum[b] = t;
    }
}

__global__ __launch_bounds__(64) void scan_p2() {
    __shared__ int sh[SCAN_NB];
    int tid = threadIdx.x;
    if (tid < SCAN_NB) sh[tid] = g_bsum[tid];
    __syncthreads();
    if (tid == 0) {
        int run = 0;
        for (int i = 0; i < SCAN_NB; i++) {
            g_boff[i] = run;
            run += sh[i];
        }
    }
}

__global__ __launch_bounds__(256) void scan_p3() {
    __shared__ int tsum[256];
    int b = blockIdx.x, tid = threadIdx.x;
    int base = b * 1024 + tid * 4;
    int v[4];
    int s = 0;
#pragma unroll
    for (int j = 0; j < 4; j++) {
        int idx = base + j;
        v[j] = (idx < NN) ? g_deg[idx] : 0;
        s += v[j];
    }
    tsum[tid] = s;
    __syncthreads();
    for (int off = 1; off < 256; off <<= 1) {
        int t = 0;
        if (tid >= off) t = tsum[tid - off];
        __syncthreads();
        tsum[tid] += t;
        __syncthreads();
    }
    int run = g_boff[b] + ((tid == 0) ? 0 : tsum[tid - 1]);
#pragma unroll
    for (int j = 0; j < 4; j++) {
        int idx = base + j;
        if (idx < NN) {
            g_rowstart[idx] = run;
            g_cursor[idx] = run;
            run += v[j];
        }
    }
}

__global__ void fill_kernel(const int* __restrict__ ei) {
    int e = blockIdx.x * blockDim.x + threadIdx.x;
    if (e < EE) {
        int d = ei[EE + e];
        int pos = atomicAdd(&g_cursor[d], 1);
        g_srclist[pos] = ei[e];
    }
}

// ---------------- GIN aggregation: one warp per node; writes packed hi/lo ----------------
__device__ __forceinline__ float4 f4add(float4 a, float4 b) {
    return make_float4(a.x + b.x, a.y + b.y, a.z + b.z, a.w + b.w);
}

__global__ __launch_bounds__(256) void gin_agg_kernel(const float* __restrict__ epsv, int layer) {
    int gtid = blockIdx.x * blockDim.x + threadIdx.x;
    int node = gtid >> 5;
    int lane = gtid & 31;
    if (node >= NN) return;
    int s = g_rowstart[node];
    int e = g_rowstart[node + 1];
    float4 acc0 = make_float4(0, 0, 0, 0);
    float4 acc1 = make_float4(0, 0, 0, 0);
    for (int i = s; i < e; i++) {
        int src = g_srclist[i];
        const float4* r = (const float4*)(g_h + (size_t)src * HH);
        acc0 = f4add(acc0, r[lane]);
        acc1 = f4add(acc1, r[lane + 32]);
    }
    float ep = 1.f + epsv[layer];
    const float4* hr = (const float4*)(g_h + (size_t)node * HH);
    float4 h0 = hr[lane], h1 = hr[lane + 32];
    acc0 = make_float4(ep * h0.x + acc0.x, ep * h0.y + acc0.y, ep * h0.z + acc0.z, ep * h0.w + acc0.w);
    acc1 = make_float4(ep * h1.x + acc1.x, ep * h1.y + acc1.y, ep * h1.z + acc1.z, ep * h1.w + acc1.w);
    // packed epilogue: word w covers cols {2w, 2w+1}
    size_t rb = (size_t)node * 128;
    uint2 H, L;
    split2(acc0.x, acc0.y, H.x, L.x);
    split2(acc0.z, acc0.w, H.y, L.y);
    *(uint2*)(g_ah + rb + 2 * lane) = H;
    *(uint2*)(g_al + rb + 2 * lane) = L;
    split2(acc1.x, acc1.y, H.x, L.x);
    split2(acc1.z, acc1.w, H.y, L.y);
    *(uint2*)(g_ah + rb + 64 + 2 * lane) = H;
    *(uint2*)(g_al + rb + 64 + 2 * lane) = L;
}

// ---------------- mma ----------------
__device__ __forceinline__ void mma16(float* d, const uint32_t* a, const uint32_t* b) {
    asm volatile(
        "mma.sync.aligned.m16n8k16.row.col.f32.bf16.bf16.f32 "
        "{%0,%1,%2,%3}, {%4,%5,%6,%7}, {%8,%9}, {%0,%1,%2,%3};"
        : "+f"(d[0]), "+f"(d[1]), "+f"(d[2]), "+f"(d[3])
        : "r"(a[0]), "r"(a[1]), "r"(a[2]), "r"(a[3]), "r"(b[0]), "r"(b[1]));
}

__device__ __forceinline__ void cpasync16(uint32_t saddr, const void* g, int n) {
    asm volatile("cp.async.ca.shared.global [%0], [%1], 16, %2;" :: "r"(saddr), "l"(g), "r"(n));
}
__device__ __forceinline__ void cpcommit() { asm volatile("cp.async.commit_group;"); }
__device__ __forceinline__ uint32_t smem_u32(const void* p) {
    uint32_t a;
    asm("{ .reg .u64 t; cvta.to.shared.u64 t, %1; cvt.u32.u64 %0, t; }" : "=r"(a) : "l"(p));
    return a;
}
__device__ __forceinline__ int swz(int row) { return ((row >> 1) & 3) << 2; }

// ---------------- pre-split GEMM: cp.async double-buffered pure-copy staging ----------------
// A packed hi/lo in g_ah/g_al (row stride KwA=128 words); B in g_wbh/g_wbl.
// 128x64 tile, K-chunk 32 (16 words). Smem: XOR-swizzled [row*16 + (w ^ swz(row))].
// MODE 0: C = A@B + bias ; MODE 1: attention logits epilogue.
template <int MODE>
__global__ __launch_bounds__(256, 2) void gemm_ps(
    int bOff, int KwB,
    const float* __restrict__ bias, float* __restrict__ C,
    int M, int N, int K,
    const float* __restrict__ ab1, const float* __restrict__ aw2,
    float* __restrict__ logits)
{
    extern __shared__ uint32_t dsm[];
    // layout (words): A: stage s hi @ s*4096, lo @ s*4096+2048 ; B: 8192 + s*2048 (+1024 lo)
    uint32_t sbase = smem_u32(dsm);

    int tid = threadIdx.x;
    int wid = tid >> 5;
    int lane = tid & 31;
    int warpM = wid >> 1;
    int warpN = wid & 1;
    int rowBase = blockIdx.y * 128;
    int colBase = blockIdx.x * 64;
    int head = (MODE == 1) ? blockIdx.z : 0;
    if (MODE == 1) bOff += head * 16384;
    const int KwA = 128;
    const uint32_t* wbh = g_wbh + bOff;
    const uint32_t* wbl = g_wbl + bOff;
    const int NC = K / 32;

    // copy-index precompute
    int arow0 = tid >> 2;            // A: j=0 rows 0..63, j=1 rows 64..127
    int aq = (tid & 3) << 2;
    int brow = tid >> 2;             // B rows 0..63
    int bq = (tid & 3) << 2;

    auto loadChunk = [&](int c, int s) {
        int kp0 = c << 4;
        uint32_t aBaseH = sbase + (s * 4096) * 4;
        uint32_t aBaseL = aBaseH + 2048 * 4;
#pragma unroll
        for (int j = 0; j < 2; j++) {
            int row = arow0 + j * 64;
            int grow = rowBase + row;
            int ok = (grow < M) ? 16 : 0;
            size_t src = (size_t)grow * KwA + kp0 + aq;
            uint32_t dw = (row * 16 + (aq ^ swz(row))) * 4;
            cpasync16(aBaseH + dw, g_ah + src, ok);
            cpasync16(aBaseL + dw, g_al + src, ok);
        }
        uint32_t bBaseH = sbase + (8192 + s * 2048) * 4;
        uint32_t bBaseL = bBaseH + 1024 * 4;
        size_t bsrc = (size_t)(colBase + brow) * KwB + kp0 + bq;
        uint32_t bdw = (brow * 16 + (bq ^ swz(brow))) * 4;
        cpasync16(bBaseH + bdw, wbh + bsrc, 16);
        cpasync16(bBaseL + bdw, wbl + bsrc, 16);
    };

    float acc[2][4][4];
#pragma unroll
    for (int mt = 0; mt < 2; mt++)
#pragma unroll
        for (int nt = 0; nt < 4; nt++)
#pragma unroll
            for (int r = 0; r < 4; r++) acc[mt][nt][r] = 0.f;

    loadChunk(0, 0);
    cpcommit();

    int t4 = lane & 3;
    for (int c = 0; c < NC; c++) {
        int cs = c & 1;
        if (c + 1 < NC) {
            loadChunk(c + 1, cs ^ 1);
            cpcommit();
            asm volatile("cp.async.wait_group 1;");
        } else {
            asm volatile("cp.async.wait_group 0;");
        }
        __syncthreads();

        const uint32_t* Ah = dsm + cs * 4096;
        const uint32_t* Al = Ah + 2048;
        const uint32_t* Bh = dsm + 8192 + cs * 2048;
        const uint32_t* Bl = Bh + 1024;

#pragma unroll
        for (int ks = 0; ks < 2; ks++) {
            int kw = ks * 8;
            uint32_t Af_h[2][4], Af_l[2][4];
#pragma unroll
            for (int mt = 0; mt < 2; mt++) {
                int r0 = warpM * 32 + mt * 16 + (lane >> 2);
                int r1 = r0 + 8;
                int s0 = swz(r0), s1 = swz(r1);
                int i00 = r0 * 16 + ((kw + t4) ^ s0);
                int i01 = r1 * 16 + ((kw + t4) ^ s1);
                int i10 = r0 * 16 + ((kw + t4 + 4) ^ s0);
                int i11 = r1 * 16 + ((kw + t4 + 4) ^ s1);
                Af_h[mt][0] = Ah[i00]; Af_h[mt][1] = Ah[i01];
                Af_h[mt][2] = Ah[i10]; Af_h[mt][3] = Ah[i11];
                Af_l[mt][0] = Al[i00]; Af_l[mt][1] = Al[i01];
                Af_l[mt][2] = Al[i10]; Af_l[mt][3] = Al[i11];
            }
            uint32_t Bf_h[4][2], Bf_l[4][2];
#pragma unroll
            for (int nt = 0; nt < 4; nt++) {
                int n = warpN * 32 + nt * 8 + (lane >> 2);
                int sn = swz(n);
                int i0 = n * 16 + ((kw + t4) ^ sn);
                int i1 = n * 16 + ((kw + t4 + 4) ^ sn);
                Bf_h[nt][0] = Bh[i0]; Bf_h[nt][1] = Bh[i1];
                Bf_l[nt][0] = Bl[i0]; Bf_l[nt][1] = Bl[i1];
            }
#pragma unroll
            for (int mt = 0; mt < 2; mt++)
#pragma unroll
                for (int nt = 0; nt < 4; nt++) {
                    mma16(acc[mt][nt], Af_h[mt], Bf_h[nt]);
                    mma16(acc[mt][nt], Af_h[mt], Bf_l[nt]);
                    mma16(acc[mt][nt], Af_l[mt], Bf_h[nt]);
                }
        }
        __syncthreads();
    }

    if (MODE == 0) {
#pragma unroll
        for (int mt = 0; mt < 2; mt++) {
            int rg = rowBase + warpM * 32 + mt * 16 + (lane >> 2);
#pragma unroll
            for (int nt = 0; nt < 4; nt++) {
                int cg = colBase + warpN * 32 + nt * 8 + 2 * (lane & 3);
                float b0 = bias[cg], b1 = bias[cg + 1];
                if (rg < M) {
                    *(float2*)(C + (size_t)rg * N + cg) =
                        make_float2(acc[mt][nt][0] + b0, acc[mt][nt][1] + b1);
                }
                if (rg + 8 < M) {
                    *(float2*)(C + (size_t)(rg + 8) * N + cg) =
                        make_float2(acc[mt][nt][2] + b0, acc[mt][nt][3] + b1);
                }
            }
        }
    } else {
        const float* b1p = ab1 + head * AA;
        const float* w2p = aw2 + head * AA;
#pragma unroll
        for (int mt = 0; mt < 2; mt++) {
            float s0 = 0.f, s1 = 0.f;
#pragma unroll
            for (int nt = 0; nt < 4; nt++) {
                int cl = colBase + warpN * 32 + nt * 8 + 2 * (lane & 3);
                float bb0 = b1p[cl], bb1 = b1p[cl + 1];
                float ww0 = w2p[cl], ww1 = w2p[cl + 1];
                s0 += tanhf(acc[mt][nt][0] + bb0) * ww0 + tanhf(acc[mt][nt][1] + bb1) * ww1;
                s1 += tanhf(acc[mt][nt][2] + bb0) * ww0 + tanhf(acc[mt][nt][3] + bb1) * ww1;
            }
            s0 += __shfl_xor_sync(0xffffffffu, s0, 1);
            s0 += __shfl_xor_sync(0xffffffffu, s0, 2);
            s1 += __shfl_xor_sync(0xffffffffu, s1, 1);
            s1 += __shfl_xor_sync(0xffffffffu, s1, 2);
            if ((lane & 3) == 0) {
                int rg = rowBase + warpM * 32 + mt * 16 + (lane >> 2);
                if (rg < M)     atomicAdd(&logits[head * NN + rg], s0);
                if (rg + 8 < M) atomicAdd(&logits[head * NN + rg + 8], s1);
            }
        }
    }
}

// ---------------- raw-A GEMM for input projection (A=x fp32, split on stage) ----------------
#define AST 17
#define BST 20

__global__ __launch_bounds__(256, 2) void gemm_raw_kernel(
    const float* __restrict__ A, int bOff, int Kw,
    const float* __restrict__ bias, float* __restrict__ C,
    int M, int N, int K)
{
    __shared__ uint32_t Ah[128 * AST];
    __shared__ uint32_t Al[128 * AST];
    __shared__ uint32_t Bh[64 * BST];
    __shared__ uint32_t Bl[64 * BST];

    int tid = threadIdx.x;
    int wid = tid >> 5;
    int lane = tid & 31;
    int warpM = wid >> 1;
    int warpN = wid & 1;
    int rowBase = blockIdx.y * 128;
    int colBase = blockIdx.x * 64;
    const uint32_t* wbh = g_wbh + bOff;
    const uint32_t* wbl = g_wbl + bOff;

    float acc[2][4][4];
#pragma unroll
    for (int mt = 0; mt < 2; mt++)
#pragma unroll
        for (int nt = 0; nt < 4; nt++)
#pragma unroll
            for (int r = 0; r < 4; r++) acc[mt][nt][r] = 0.f;

    for (int k0 = 0; k0 < K; k0 += 32) {
        int kp0 = k0 >> 1;
#pragma unroll
        for (int i = 0; i < 4; i++) {
            int f4id = tid + 256 * i;
            int row = f4id >> 3;
            int kc = (f4id & 7) << 2;
            int grow = rowBase + row;
            float4 v = make_float4(0, 0, 0, 0);
            if (grow < M) v = *(const float4*)(A + (size_t)grow * K + k0 + kc);
            uint32_t h01, l01, h23, l23;
            split2(v.x, v.y, h01, l01);
            split2(v.z, v.w, h23, l23);
            int w = row * AST + (kc >> 1);
            Ah[w] = h01; Ah[w + 1] = h23;
            Al[w] = l01; Al[w + 1] = l23;
        }
        {
            int row = tid >> 2;
            int q = (tid & 3) << 2;
            size_t src = (size_t)(colBase + row) * Kw + kp0 + q;
            *(uint4*)&Bh[row * BST + q] = *(const uint4*)(wbh + src);
            *(uint4*)&Bl[row * BST + q] = *(const uint4*)(wbl + src);
        }
        __syncthreads();

#pragma unroll
        for (int ks = 0; ks < 2; ks++) {
            int kw = ks * 8;
            uint32_t Af_h[2][4], Af_l[2][4];
#pragma unroll
            for (int mt = 0; mt < 2; mt++) {
                int mrow = warpM * 32 + mt * 16 + (lane >> 2);
                int base = mrow * AST + kw + (lane & 3);
                Af_h[mt][0] = Ah[base];
                Af_h[mt][1] = Ah[base + 8 * AST];
                Af_h[mt][2] = Ah[base + 4];
                Af_h[mt][3] = Ah[base + 8 * AST + 4];
                Af_l[mt][0] = Al[base];
                Af_l[mt][1] = Al[base + 8 * AST];
                Af_l[mt][2] = Al[base + 4];
                Af_l[mt][3] = Al[base + 8 * AST + 4];
            }
            uint32_t Bf_h[4][2], Bf_l[4][2];
#pragma unroll
            for (int nt = 0; nt < 4; nt++) {
                int n = warpN * 32 + nt * 8 + (lane >> 2);
                int bb = n * BST + kw + (lane & 3);
                Bf_h[nt][0] = Bh[bb];
                Bf_h[nt][1] = Bh[bb + 4];
                Bf_l[nt][0] = Bl[bb];
                Bf_l[nt][1] = Bl[bb + 4];
            }
#pragma unroll
            for (int mt = 0; mt < 2; mt++)
#pragma unroll
                for (int nt = 0; nt < 4; nt++) {
                    mma16(acc[mt][nt], Af_h[mt], Bf_h[nt]);
                    mma16(acc[mt][nt], Af_h[mt], Bf_l[nt]);
                    mma16(acc[mt][nt], Af_l[mt], Bf_h[nt]);
                }
        }
        __syncthreads();
    }

#pragma unroll
    for (int mt = 0; mt < 2; mt++) {
        int rg = rowBase + warpM * 32 + mt * 16 + (lane >> 2);
#pragma unroll
        for (int nt = 0; nt < 4; nt++) {
            int cg = colBase + warpN * 32 + nt * 8 + 2 * (lane & 3);
            float b0 = bias[cg], b1 = bias[cg + 1];
            if (rg < M) {
                *(float2*)(C + (size_t)rg * N + cg) =
                    make_float2(acc[mt][nt][0] + b0, acc[mt][nt][1] + b1);
            }
            if (rg + 8 < M) {
                *(float2*)(C + (size_t)(rg + 8) * N + cg) =
                    make_float2(acc[mt][nt][2] + b0, acc[mt][nt][3] + b1);
            }
        }
    }
}

// ---------------- LayerNorm (+relu, + optional residual), warp per row ----------------
// float2-pair layout; writes fp32 (outf) and/or packed hi/lo (wpack)
__global__ __launch_bounds__(256) void ln_relu_kernel(
    const float* __restrict__ in, const float* __restrict__ gamma,
    const float* __restrict__ beta, const float* __restrict__ resid,
    float* __restrict__ outf, int wpack)
{
    int gtid = blockIdx.x * blockDim.x + threadIdx.x;
    int row = gtid >> 5;
    int lane = gtid & 31;
    if (row >= NN) return;
    const float2* r = (const float2*)(in + (size_t)row * HH);
    float2 v[4];
    float s = 0.f, sq = 0.f;
#pragma unroll
    for (int j = 0; j < 4; j++) {
        float2 x = r[lane + 32 * j];
        v[j] = x;
        s += x.x + x.y;
        sq += x.x * x.x + x.y * x.y;
    }
#pragma unroll
    for (int off = 16; off; off >>= 1) {
        s  += __shfl_xor_sync(0xffffffffu, s, off);
        sq += __shfl_xor_sync(0xffffffffu, sq, off);
    }
    float mean = s * (1.f / HH);
    float var  = sq * (1.f / HH) - mean * mean;
    float rstd = rsqrtf(var + 1e-5f);
    const float2* g2 = (const float2*)gamma;
    const float2* b2 = (const float2*)beta;
    const float2* rr = resid ? (const float2*)(resid + (size_t)row * HH) : nullptr;
    float2* o2 = outf ? (float2*)(outf + (size_t)row * HH) : nullptr;
    size_t prow = (size_t)row * 128;
#pragma unroll
    for (int j = 0; j < 4; j++) {
        int w = lane + 32 * j;
        float2 gv = g2[w], bv = b2[w];
        float y0 = fmaxf((v[j].x - mean) * rstd * gv.x + bv.x, 0.f);
        float y1 = fmaxf((v[j].y - mean) * rstd * gv.y + bv.y, 0.f);
        if (rr) {
            float2 rv = rr[w];
            y0 += rv.x; y1 += rv.y;
        }
        if (o2) o2[w] = make_float2(y0, y1);
        if (wpack) {
            uint32_t hi, lo;
            split2(y0, y1, hi, lo);
            g_ah[prow + w] = hi;
            g_al[prow + w] = lo;
        }
    }
}

// ---------------- softmax stats: one block per head ----------------
__global__ __launch_bounds__(1024) void softmax_stats_kernel() {
    int k = blockIdx.x;
    const float* l = g_logits + k * NN;
    __shared__ float red[1024];
    int tid = threadIdx.x;
    float mx = -1e30f;
    for (int i = tid; i < NN; i += 1024) mx = fmaxf(mx, l[i]);
    red[tid] = mx;
    __syncthreads();
    for (int off = 512; off; off >>= 1) {
        if (tid < off) red[tid] = fmaxf(red[tid], red[tid + off]);
        __syncthreads();
    }
    mx = red[0];
    __syncthreads();
    float s = 0.f;
    for (int i = tid; i < NN; i += 1024) s += expf(l[i] - mx);
    red[tid] = s;
    __syncthreads();
    for (int off = 512; off; off >>= 1) {
        if (tid < off) red[tid] += red[tid + off];
        __syncthreads();
    }
    if (tid == 0) {
        g_smax[k]  = mx;
        g_srsum[k] = 1.f / red[0];
    }
}

// ---------------- pooling ----------------
__global__ __launch_bounds__(256) void pool_kernel(const float* __restrict__ h, float* __restrict__ out) {
    __shared__ float a_s[256 * 4];
    int tid = threadIdx.x;
    int n0 = blockIdx.x * 256;
    int n = n0 + tid;
#pragma unroll
    for (int k = 0; k < AHD; k++) {
        float a = 0.f;
        if (n < NN) {
            a = expf(g_logits[k * NN + n] - g_smax[k]) * g_srsum[k];
            out[7 + (size_t)n * AHD + k] = a;
        }
        a_s[tid * 4 + k] = a;
    }
    __syncthreads();
    float zr[4] = {0.f, 0.f, 0.f, 0.f};
    int nmax = min(256, NN - n0);
    for (int i = 0; i < nmax; i++) {
        float hv = h[(size_t)(n0 + i) * HH + tid];
        float4 av = *(float4*)&a_s[i * 4];
        zr[0] += av.x * hv;
        zr[1] += av.y * hv;
        zr[2] += av.z * hv;
        zr[3] += av.w * hv;
    }
#pragma unroll
    for (int k = 0; k < AHD; k++) atomicAdd(&g_z[k * HH + tid], zr[k]);
}

// ---------------- classifier ----------------
__global__ __launch_bounds__(256) void classifier_kernel(
    const float* __restrict__ Wc1, const float* __restrict__ bc1,
    const float* __restrict__ g1,  const float* __restrict__ b1,
    const float* __restrict__ Wc2, const float* __restrict__ bc2,
    const float* __restrict__ g2,  const float* __restrict__ b2,
    const float* __restrict__ Wc3, const float* __restrict__ bc3,
    float* __restrict__ out)
{
    __shared__ float sh[256];
    __shared__ float redA[256];
    __shared__ float redB[256];
    int tid = threadIdx.x;
    float za = 0.25f * (g_z[tid] + g_z[256 + tid] + g_z[512 + tid] + g_z[768 + tid]);
    sh[tid] = za;
    __syncthreads();

    float c = 0.f;
    if (tid < 128) {
        for (int d = 0; d < 256; d++) c += sh[d] * Wc1[d * 128 + tid];
        c += bc1[tid];
    }
    redA[tid] = (tid < 128) ? c : 0.f;
    redB[tid] = (tid < 128) ? c * c : 0.f;
    __syncthreads();
    for (int off = 128; off; off >>= 1) {
        if (tid < off) { redA[tid] += redA[tid + off]; redB[tid] += redB[tid + off]; }
        __syncthreads();
    }
    float mean = redA[0] / 128.f;
    float var  = redB[0] / 128.f - mean * mean;
    float rstd = rsqrtf(var + 1e-5f);
    __syncthreads();
    if (tid < 128) sh[tid] = fmaxf((c - mean) * rstd * g1[tid] + b1[tid], 0.f);
    __syncthreads();

    float c2 = 0.f;
    if (tid < 64) {
        for (int d = 0; d < 128; d++) c2 += sh[d] * Wc2[d * 64 + tid];
        c2 += bc2[tid];
    }
    redA[tid] = (tid < 64) ? c2 : 0.f;
    redB[tid] = (tid < 64) ? c2 * c2 : 0.f;
    __syncthreads();
    for (int off = 128; off; off >>= 1) {
        if (tid < off) { redA[tid] += redA[tid + off]; redB[tid] += redB[tid + off]; }
        __syncthreads();
    }
    mean = redA[0] / 64.f;
    var  = redB[0] / 64.f - mean * mean;
    rstd = rsqrtf(var + 1e-5f);
    __syncthreads();
    if (tid < 64) sh[tid] = fmaxf((c2 - mean) * rstd * g2[tid] + b2[tid], 0.f);
    __syncthreads();

    if (tid < NCLS) {
        float lg = 0.f;
        for (int d = 0; d < 64; d++) lg += sh[d] * Wc3[d * NCLS + tid];
        redA[tid] = lg + bc3[tid];
    }
    __syncthreads();
    if (tid == 0) {
        float mx = -1e30f;
        for (int i = 0; i < NCLS; i++) mx = fmaxf(mx, redA[i]);
        float s = 0.f;
        for (int i = 0; i < NCLS; i++) s += expf(redA[i] - mx);
        float rs = 1.f / s;
        for (int i = 0; i < NCLS; i++) out[i] = expf(redA[i] - mx) * rs;
    }
}

// ---------------- launcher ----------------
extern "C" void kernel_launch(void* const* d_in, const int* in_sizes, int n_in,
                              void* d_out, int out_size)
{
    const float* x     = (const float*)d_in[0];
    const int*   ei    = (const int*)  d_in[1];
    const float* W_in  = (const float*)d_in[2];
    const float* b_in  = (const float*)d_in[3];
    const float* gW1   = (const float*)d_in[4];
    const float* gb1   = (const float*)d_in[5];
    const float* glng  = (const float*)d_in[6];
    const float* glnb  = (const float*)d_in[7];
    const float* gW2   = (const float*)d_in[8];
    const float* gb2   = (const float*)d_in[9];
    const float* eps   = (const float*)d_in[10];
    const float* lng   = (const float*)d_in[11];
    const float* lnb   = (const float*)d_in[12];
    const float* aW1   = (const float*)d_in[13];
    const float* ab1   = (const float*)d_in[14];
    const float* aW2   = (const float*)d_in[15];
    const float* Wc1   = (const float*)d_in[17];
    const float* bc1   = (const float*)d_in[18];
    const float* lc1g  = (const float*)d_in[19];
    const float* lc1b  = (const float*)d_in[20];
    const float* Wc2   = (const float*)d_in[21];
    const float* bc2   = (const float*)d_in[22];
    const float* lc2g  = (const float*)d_in[23];
    const float* lc2b  = (const float*)d_in[24];
    const float* Wc3   = (const float*)d_in[25];
    const float* bc3   = (const float*)d_in[26];
    float* out = (float*)d_out;

    float *p_h, *p_t, *p_logits;
    cudaGetSymbolAddress((void**)&p_h, g_h);
    cudaGetSymbolAddress((void**)&p_t, g_t);
    cudaGetSymbolAddress((void**)&p_logits, g_logits);

    const int SMEM_PS = 12288 * 4;   // 48KB dynamic
    cudaFuncSetAttribute(gemm_ps<0>, cudaFuncAttributeMaxDynamicSharedMemorySize, SMEM_PS);
    cudaFuncSetAttribute(gemm_ps<1>, cudaFuncAttributeMaxDynamicSharedMemorySize, SMEM_PS);

    const int MB = (NN + 127) / 128;               // 391 row tiles
    const int WARP_BLKS = (NN * 32 + 255) / 256;   // 6250
    const int ROW_BLKS  = (NN + 7) / 8;            // 6250
    const int EDGE_BLKS = (EE + 255) / 256;        // 3125
    const int POOL_BLKS = (NN + 255) / 256;        // 196
    const int ZERO_BLKS = (AHD * NN + 255) / 256;  // 782
    const int WS_BLKS   = (WSPLIT_TOTAL + 255) / 256;

    // weight pre-split + CSR build + scratch zero
    wsplit_kernel<<<WS_BLKS, 256>>>(W_in, gW1, gW2, aW1);
    zero_kernel<<<ZERO_BLKS, 256>>>();
    hist_kernel<<<EDGE_BLKS, 256>>>(ei);
    scan_p1<<<SCAN_NB, 256>>>();
    scan_p2<<<1, 64>>>();
    scan_p3<<<SCAN_NB, 256>>>();
    fill_kernel<<<EDGE_BLKS, 256>>>(ei);

    // input projection: h = x @ W_in + b_in  (raw-A path)
    gemm_raw_kernel<<<dim3(HH / 64, MB), 256>>>(
        x, OFF_WIN, FF / 2, b_in, p_h, NN, HH, FF);

    // GIN layers: agg/t pre-split by producers, GEMMs pure-copy + cp.async
    for (int l = 0; l < 2; l++) {
        gin_agg_kernel<<<WARP_BLKS, 256>>>(eps, l);
        gemm_ps<0><<<dim3(HH / 64, MB), 256, SMEM_PS>>>(
            OFF_GW1 + l * 32768, HH / 2, gb1 + l * HH, p_t,
            NN, HH, HH, nullptr, nullptr, nullptr);
        ln_relu_kernel<<<ROW_BLKS, 256>>>(p_t, glng + l * HH, glnb + l * HH, nullptr,
                                          nullptr, 1);
        gemm_ps<0><<<dim3(HH / 64, MB), 256, SMEM_PS>>>(
            OFF_GW2 + l * 32768, HH / 2, gb2 + l * HH, p_t,
            NN, HH, HH, nullptr, nullptr, nullptr);
        // residual LN: writes fp32 h always; packed h only after last layer (for attention)
        ln_relu_kernel<<<ROW_BLKS, 256>>>(p_t, lng + l * HH, lnb + l * HH, p_h,
                                          p_h, (l == 1) ? 1 : 0);
    }

    // attention logits from packed h
    gemm_ps<1><<<dim3(AA / 64, MB, AHD), 256, SMEM_PS>>>(
        OFF_AW1, AA, nullptr, nullptr, NN, AA, HH, ab1, aW2, p_logits);

    softmax_stats_kernel<<<AHD, 1024>>>();
    pool_kernel<<<POOL_BLKS, 256>>>(p_h, out);

    // classifier head
    classifier_kernel<<<1, 256>>>(Wc1, bc1, lc1g, lc1b, Wc2, bc2, lc2g, lc2b, Wc3, bc3, out);
}